// round 8
// baseline (speedup 1.0000x reference)
#include <cuda_runtime.h>
#include <cstdint>

typedef unsigned long long ull;

// Packed f32x2 FMA / ADD — only reachable via PTX (ptxas never auto-fuses).
#define FMA2(d, a, b, c) \
    asm("fma.rn.f32x2 %0, %1, %2, %3;" : "=l"(d) : "l"(a), "l"(b), "l"(c))
#define ADD2(d, a, b) \
    asm("add.rn.f32x2 %0, %1, %2;" : "=l"(d) : "l"(a), "l"(b))

__device__ __forceinline__ ull pack2(float lo, float hi) {
    ull r;
    asm("mov.b64 %0, {%1, %2};" : "=l"(r) : "f"(lo), "f"(hi));
    return r;
}
__device__ __forceinline__ void stg_cs(float* p, ull v) {
    asm volatile("st.global.cs.b64 [%0], %1;" :: "l"(p), "l"(v) : "memory");
}

namespace {
constexpr int H  = 224;
constexpr int W  = 224;
constexpr int HO = 222;
constexpr int WO = 222;
constexpr int OC = 64;
constexpr int TPB = 256;       // 8 warps = 8 channels
constexpr int RS  = 24;        // output rows per strip (divisible by 3)
constexpr int NSTRIP = 10;     // 9 full strips + one 6-row strip (6 % 3 == 0)
constexpr int SPITCH = 68;     // smem row pitch (floats)
constexpr int SROWS  = RS + 2; // 26 staged input rows
}

// Block: 8 channels x 64 cols x <=24 rows x 1 batch.
// Warp = one channel; lane = 2 cols; loop over strip rows with register
// weights and a 3-row rotating packed-pair window.
// Grid (4 chunks x 10 strips, 8 ch-groups, 32 b) = 10240 blocks, 2.6M threads.
__global__ __launch_bounds__(TPB, 5)
void Conv2d_68298569941797_kernel(const float* __restrict__ data,
                                  const float* __restrict__ weight,
                                  float* __restrict__ out) {
    __shared__ float s_in[SROWS * SPITCH];   // 26 x 68 floats ~= 7 KB

    const int tid   = threadIdx.x;
    const int wid   = tid >> 5;
    const int lane  = tid & 31;
    const int c     = blockIdx.x & 3;        // x chunk 0..3
    const int strip = blockIdx.x >> 2;       // 0..9
    const int b     = blockIdx.z;
    const int ch    = blockIdx.y * 8 + wid;
    const int xbase = 64 * c;
    const int y0    = strip * RS;                     // first output row
    const int nrows = (strip == NSTRIP - 1) ? (HO - y0) : RS;  // 24 or 6
    const int cols  = (xbase + SPITCH <= W) ? SPITCH : (W - xbase);  // 68 or 32
    const int nvec  = cols >> 2;             // float4s per staged row

    // ── Stage input rows y0 .. y0+nrows+1 (cols xbase..xbase+cols-1) ──
    const float* dsrc = data + (size_t)b * H * W + xbase;
    const int tot = (nrows + 2) * nvec;
    for (int i = tid; i < tot; i += TPB) {
        int rr = i / nvec;
        int v  = i - rr * nvec;
        *reinterpret_cast<float4*>(s_in + rr * SPITCH + 4 * v) =
            *reinterpret_cast<const float4*>(dsrc + (size_t)(y0 + rr) * W + 4 * v);
    }

    // Weights for this warp's channel: 9 taps, duplicated into both f32x2 lanes.
    ull wreg[9];
#pragma unroll
    for (int k = 0; k < 9; ++k) {
        float wv = __ldg(weight + ch * 9 + k);
        wreg[k] = pack2(wv, wv);
    }
    __syncthreads();

    const int x = xbase + 2 * lane;          // lane's output col pair
    if (x + 1 >= WO) return;                 // chunk 3: lanes 15..31 idle
    const int lc = 2 * lane;                 // local col in strip

    // Prime the 3-row sliding pair window with strip rows 0 and 1.
    ull P[3][3];
#pragma unroll
    for (int rr = 0; rr < 2; ++rr) {
        float2 u = *reinterpret_cast<const float2*>(s_in + rr * SPITCH + lc);
        float2 v = *reinterpret_cast<const float2*>(s_in + rr * SPITCH + lc + 2);
        P[rr][0] = pack2(u.x, u.y);
        P[rr][1] = pack2(u.y, v.x);
        P[rr][2] = pack2(v.x, v.y);
    }

    float* op = out + (((size_t)b * OC + ch) * HO + y0) * WO + x;

#pragma unroll 3
    for (int ly = 0; ly < nrows; ++ly) {
        // Load the new bottom row (strip row ly+2) into the rotating slot.
        const int rn = (ly + 2) % 3;
        {
            const float* rp = s_in + (ly + 2) * SPITCH + lc;
            float2 u = *reinterpret_cast<const float2*>(rp);
            float2 v = *reinterpret_cast<const float2*>(rp + 2);
            P[rn][0] = pack2(u.x, u.y);
            P[rn][1] = pack2(u.y, v.x);
            P[rn][2] = pack2(v.x, v.y);
        }
        const int r0 = ly % 3;
        const int r1 = (ly + 1) % 3;
        const int r2 = rn;

        // Two independent chains, joined once.
        ull Aa = 0ull, Ab = 0ull;
        FMA2(Aa, P[r0][0], wreg[0], Aa);
        FMA2(Ab, P[r0][1], wreg[1], Ab);
        FMA2(Aa, P[r0][2], wreg[2], Aa);
        FMA2(Ab, P[r1][0], wreg[3], Ab);
        FMA2(Aa, P[r1][1], wreg[4], Aa);
        FMA2(Ab, P[r1][2], wreg[5], Ab);
        FMA2(Aa, P[r2][0], wreg[6], Aa);
        FMA2(Ab, P[r2][1], wreg[7], Ab);
        FMA2(Aa, P[r2][2], wreg[8], Aa);
        ull acc;
        ADD2(acc, Aa, Ab);

        stg_cs(op, acc);               // STG.64, coalesced, evict-first
        op += WO;
    }
}

extern "C" void kernel_launch(void* const* d_in, const int* in_sizes, int n_in,
                              void* d_out, int out_size) {
    const float* data   = (const float*)d_in[0];
    const float* weight = (const float*)d_in[1];
    float* out          = (float*)d_out;

    dim3 grid(4 * NSTRIP, OC / 8, 32);   // (40, 8, 32) = 10240 blocks
    Conv2d_68298569941797_kernel<<<grid, TPB>>>(data, weight, out);
}

// round 10
// speedup vs baseline: 2.7730x; 2.7730x over previous
#include <cuda_runtime.h>
#include <cstdint>

typedef unsigned long long ull;

// Packed f32x2 FMA / ADD — only reachable via PTX (ptxas never auto-fuses).
#define FMA2(d, a, b, c) \
    asm("fma.rn.f32x2 %0, %1, %2, %3;" : "=l"(d) : "l"(a), "l"(b), "l"(c))
#define ADD2(d, a, b) \
    asm("add.rn.f32x2 %0, %1, %2;" : "=l"(d) : "l"(a), "l"(b))

__device__ __forceinline__ ull pack2(float lo, float hi) {
    ull r;
    asm("mov.b64 %0, {%1, %2};" : "=l"(r) : "f"(lo), "f"(hi));
    return r;
}
__device__ __forceinline__ void stg_cs(float* p, ull v) {
    asm volatile("st.global.cs.b64 [%0], %1;" :: "l"(p), "l"(v) : "memory");
}

namespace {
constexpr int H  = 224;
constexpr int W  = 224;
constexpr int HO = 222;
constexpr int WO = 222;
constexpr int OC = 64;
constexpr int TPB = 256;       // 8 warps = 8 channels
constexpr int RS  = 24;        // output rows per full strip (divisible by 3)
constexpr int NSTRIP = 10;     // 9 full strips + one 6-row strip
constexpr int SPITCH = 68;     // smem row pitch (floats)
constexpr int SROWS  = RS + 2; // staged input rows (max)
}

// Compile-time trip count => every P index is static => P stays in registers.
template <int NR>
__device__ __forceinline__ void row_loop(const float* s_row0, const ull* wreg,
                                         float* op) {
    // Prime the 3-row sliding pair window with strip rows 0 and 1.
    ull P[3][3];
#pragma unroll
    for (int rr = 0; rr < 2; ++rr) {
        float2 u = *reinterpret_cast<const float2*>(s_row0 + rr * SPITCH);
        float2 v = *reinterpret_cast<const float2*>(s_row0 + rr * SPITCH + 2);
        P[rr][0] = pack2(u.x, u.y);
        P[rr][1] = pack2(u.y, v.x);
        P[rr][2] = pack2(v.x, v.y);
    }

#pragma unroll
    for (int ly = 0; ly < NR; ++ly) {
        const int rn = (ly + 2) % 3;       // constexpr per unrolled iteration
        {
            const float* rp = s_row0 + (ly + 2) * SPITCH;
            float2 u = *reinterpret_cast<const float2*>(rp);
            float2 v = *reinterpret_cast<const float2*>(rp + 2);
            P[rn][0] = pack2(u.x, u.y);
            P[rn][1] = pack2(u.y, v.x);
            P[rn][2] = pack2(v.x, v.y);
        }
        const int r0 = ly % 3;
        const int r1 = (ly + 1) % 3;
        const int r2 = rn;

        ull Aa = 0ull, Ab = 0ull;          // two independent chains
        FMA2(Aa, P[r0][0], wreg[0], Aa);
        FMA2(Ab, P[r0][1], wreg[1], Ab);
        FMA2(Aa, P[r0][2], wreg[2], Aa);
        FMA2(Ab, P[r1][0], wreg[3], Ab);
        FMA2(Aa, P[r1][1], wreg[4], Aa);
        FMA2(Ab, P[r1][2], wreg[5], Ab);
        FMA2(Aa, P[r2][0], wreg[6], Aa);
        FMA2(Ab, P[r2][1], wreg[7], Ab);
        FMA2(Aa, P[r2][2], wreg[8], Aa);
        ull acc;
        ADD2(acc, Aa, Ab);

        stg_cs(op, acc);                   // STG.64, coalesced, evict-first
        op += WO;
    }
}

// Block: 8 channels x 64 cols x <=24 rows x 1 batch.
// Warp = one channel; lane = 2 cols; register weights + 3-row sliding window.
// Grid (4 chunks x 10 strips, 8 ch-groups, 32 b) = 10240 blocks, 2.6M threads.
__global__ __launch_bounds__(TPB, 5)
void Conv2d_68298569941797_kernel(const float* __restrict__ data,
                                  const float* __restrict__ weight,
                                  float* __restrict__ out) {
    __shared__ float s_in[SROWS * SPITCH];   // 26 x 68 floats ~= 7 KB

    const int tid   = threadIdx.x;
    const int wid   = tid >> 5;
    const int lane  = tid & 31;
    const int c     = blockIdx.x & 3;        // x chunk 0..3
    const int strip = blockIdx.x >> 2;       // 0..9
    const int b     = blockIdx.z;
    const int ch    = blockIdx.y * 8 + wid;
    const int xbase = 64 * c;
    const int y0    = strip * RS;
    const bool full = (strip != NSTRIP - 1); // 24-row vs 6-row strip
    const int nrows = full ? RS : (HO - y0);
    const int cols  = (xbase + SPITCH <= W) ? SPITCH : (W - xbase);  // 68 or 32
    const int nvec  = cols >> 2;

    // ── Stage input rows y0 .. y0+nrows+1 ──
    const float* dsrc = data + (size_t)b * H * W + xbase;
    const int tot = (nrows + 2) * nvec;
    for (int i = tid; i < tot; i += TPB) {
        int rr = i / nvec;
        int v  = i - rr * nvec;
        *reinterpret_cast<float4*>(s_in + rr * SPITCH + 4 * v) =
            *reinterpret_cast<const float4*>(dsrc + (size_t)(y0 + rr) * W + 4 * v);
    }

    // Weights for this warp's channel: 9 taps, duplicated into both f32x2 lanes.
    ull wreg[9];
#pragma unroll
    for (int k = 0; k < 9; ++k) {
        float wv = __ldg(weight + ch * 9 + k);
        wreg[k] = pack2(wv, wv);
    }
    __syncthreads();

    const int x = xbase + 2 * lane;          // lane's output col pair
    if (x + 1 >= WO) return;                 // chunk 3: lanes 15..31 idle
    const int lc = 2 * lane;

    float* op = out + (((size_t)b * OC + ch) * HO + y0) * WO + x;
    const float* s0 = s_in + lc;

    if (full) row_loop<RS>(s0, wreg, op);
    else      row_loop<HO - (NSTRIP - 1) * RS>(s0, wreg, op);   // 6 rows
}

extern "C" void kernel_launch(void* const* d_in, const int* in_sizes, int n_in,
                              void* d_out, int out_size) {
    const float* data   = (const float*)d_in[0];
    const float* weight = (const float*)d_in[1];
    float* out          = (float*)d_out;

    dim3 grid(4 * NSTRIP, OC / 8, 32);   // (40, 8, 32) = 10240 blocks
    Conv2d_68298569941797_kernel<<<grid, TPB>>>(data, weight, out);
}

// round 11
// speedup vs baseline: 2.9068x; 1.0483x over previous
#include <cuda_runtime.h>
#include <cstdint>

typedef unsigned long long ull;

// Packed f32x2 FMA / ADD — only reachable via PTX (ptxas never auto-fuses).
#define FMA2(d, a, b, c) \
    asm("fma.rn.f32x2 %0, %1, %2, %3;" : "=l"(d) : "l"(a), "l"(b), "l"(c))
#define ADD2(d, a, b) \
    asm("add.rn.f32x2 %0, %1, %2;" : "=l"(d) : "l"(a), "l"(b))

__device__ __forceinline__ ull pack2(float lo, float hi) {
    ull r;
    asm("mov.b64 %0, {%1, %2};" : "=l"(r) : "f"(lo), "f"(hi));
    return r;
}

namespace {
constexpr int H  = 224;
constexpr int W  = 224;
constexpr int HO = 222;
constexpr int WO = 222;
constexpr int OC = 64;
constexpr int TPB = 256;       // 8 warps = 2 channels x 4 x-chunks
constexpr int RS  = 24;        // output rows per full strip (divisible by 3)
constexpr int NSTRIP = 10;     // 9 full strips + one 6-row strip
constexpr int SPITCH = 228;    // full-width smem row pitch (floats, /4)
constexpr int SROWS  = RS + 2; // staged input rows (max)
}

// Compile-time trip count => every P index is static => P stays in registers.
template <int NR>
__device__ __forceinline__ void row_loop(const float* s_row0, const ull* wreg,
                                         float* op) {
    // Prime the 3-row sliding pair window with strip rows 0 and 1.
    ull P[3][3];
#pragma unroll
    for (int rr = 0; rr < 2; ++rr) {
        float2 u = *reinterpret_cast<const float2*>(s_row0 + rr * SPITCH);
        float2 v = *reinterpret_cast<const float2*>(s_row0 + rr * SPITCH + 2);
        P[rr][0] = pack2(u.x, u.y);
        P[rr][1] = pack2(u.y, v.x);
        P[rr][2] = pack2(v.x, v.y);
    }

#pragma unroll
    for (int ly = 0; ly < NR; ++ly) {
        const int rn = (ly + 2) % 3;       // constexpr per unrolled iteration
        {
            const float* rp = s_row0 + (ly + 2) * SPITCH;
            float2 u = *reinterpret_cast<const float2*>(rp);
            float2 v = *reinterpret_cast<const float2*>(rp + 2);
            P[rn][0] = pack2(u.x, u.y);
            P[rn][1] = pack2(u.y, v.x);
            P[rn][2] = pack2(v.x, v.y);
        }
        const int r0 = ly % 3;
        const int r1 = (ly + 1) % 3;
        const int r2 = rn;

        ull Aa = 0ull, Ab = 0ull;          // two independent chains
        FMA2(Aa, P[r0][0], wreg[0], Aa);
        FMA2(Ab, P[r0][1], wreg[1], Ab);
        FMA2(Aa, P[r0][2], wreg[2], Aa);
        FMA2(Ab, P[r1][0], wreg[3], Ab);
        FMA2(Aa, P[r1][1], wreg[4], Aa);
        FMA2(Ab, P[r1][2], wreg[5], Ab);
        FMA2(Aa, P[r2][0], wreg[6], Aa);
        FMA2(Ab, P[r2][1], wreg[7], Ab);
        FMA2(Aa, P[r2][2], wreg[8], Aa);
        ull acc;
        ADD2(acc, Aa, Ab);

        *reinterpret_cast<ull*>(op) = acc;  // STG.64, coalesced
        op += WO;
    }
}

// Block: 2 channels x FULL 222-col rows x <=24 rows x 1 batch.
// Warp = (ch_local, x-chunk); lane = 2 cols. All writes of a (ch, strip)
// region are contiguous (24 x 888 B) and issued by one block -> L2 merges
// full 128B lines regardless of inter-block scheduling.
__global__ __launch_bounds__(TPB, 5)
void Conv2d_68298569941797_kernel(const float* __restrict__ data,
                                  const float* __restrict__ weight,
                                  float* __restrict__ out) {
    __shared__ float s_in[SROWS * SPITCH];   // 26 x 228 floats ~= 23.7 KB

    const int tid   = threadIdx.x;
    const int wid   = tid >> 5;
    const int lane  = tid & 31;
    const int chl   = wid >> 2;              // channel within block: 0..1
    const int chunk = wid & 3;               // x chunk: 0..3
    const int strip = blockIdx.x;            // 0..9
    const int b     = blockIdx.z;
    const int ch    = blockIdx.y * 2 + chl;
    const int y0    = strip * RS;
    const bool full = (strip != NSTRIP - 1); // 24-row vs 6-row strip
    const int nrows = full ? RS : (HO - y0);

    // ── Stage input rows y0 .. y0+nrows+1, full width (224 floats = 56 f4) ──
    const float* dsrc = data + (size_t)b * H * W;
    const int tot = (nrows + 2) * 56;
    for (int i = tid; i < tot; i += TPB) {
        int rr = i / 56;
        int v  = i - rr * 56;
        *reinterpret_cast<float4*>(s_in + rr * SPITCH + 4 * v) =
            *reinterpret_cast<const float4*>(dsrc + (size_t)(y0 + rr) * W + 4 * v);
    }

    // Weights for this warp's channel: 9 taps, duplicated into both f32x2 lanes.
    ull wreg[9];
#pragma unroll
    for (int k = 0; k < 9; ++k) {
        float wv = __ldg(weight + ch * 9 + k);
        wreg[k] = pack2(wv, wv);
    }
    __syncthreads();

    const int x = 64 * chunk + 2 * lane;     // lane's output col pair
    if (x + 1 >= WO) return;                 // chunk 3: lanes 15..31 idle

    float* op = out + (((size_t)b * OC + ch) * HO + y0) * WO + x;
    const float* s0 = s_in + x;

    if (full) row_loop<RS>(s0, wreg, op);
    else      row_loop<HO - (NSTRIP - 1) * RS>(s0, wreg, op);   // 6 rows
}

extern "C" void kernel_launch(void* const* d_in, const int* in_sizes, int n_in,
                              void* d_out, int out_size) {
    const float* data   = (const float*)d_in[0];
    const float* weight = (const float*)d_in[1];
    float* out          = (float*)d_out;

    dim3 grid(NSTRIP, OC / 2, 32);   // (10, 32, 32) = 10240 blocks
    Conv2d_68298569941797_kernel<<<grid, TPB>>>(data, weight, out);
}

// round 12
// speedup vs baseline: 3.1372x; 1.0793x over previous
#include <cuda_runtime.h>
#include <cstdint>

typedef unsigned long long ull;

// Packed f32x2 FMA — only reachable via PTX (ptxas never auto-fuses 2x fmaf).
#define FMA2(d, a, b, c) \
    asm("fma.rn.f32x2 %0, %1, %2, %3;" : "=l"(d) : "l"(a), "l"(b), "l"(c))

__device__ __forceinline__ ull pack2(float lo, float hi) {
    ull r;
    asm("mov.b64 %0, {%1, %2};" : "=l"(r) : "f"(lo), "f"(hi));
    return r;
}

namespace {
constexpr int H  = 224;
constexpr int W  = 224;
constexpr int HO = 222;
constexpr int WO = 222;
constexpr int OC = 64;
constexpr int TPB = 224;   // 2 rows x 112 pair-slots (111 active: 99.1% lanes)
}

// R1 geometry (the measured-best): block = 2 output rows x 222 cols x 64 ch,
// thread = 1 row x 2 cols x 64 channels, weights from smem (broadcast LDS.128).
// Deltas vs R1: TPB 256->224 (lane waste 13%->0.9%), launch_bounds(224,5)
// (occ 46%->55% theoretical, reg cap 58 > R1's 56 so no spill).
__global__ __launch_bounds__(TPB, 5)
void Conv2d_68298569941797_kernel(const float* __restrict__ data,
                                  const float* __restrict__ weight,
                                  float* __restrict__ out) {
    __shared__ float s_in[4 * W];          // input rows y0..y0+3
    __shared__ ull   s_w[OC * 10];         // 9 packed (w,w) + pad -> LDS.128-friendly

    const int tid = threadIdx.x;
    const int b   = blockIdx.y;
    const int y0  = blockIdx.x * 2;

    // Stage 4 input rows (y0 <= 220 -> rows <= 223, in bounds).
    const float* src = data + ((size_t)b * H + y0) * W;
    for (int i = tid; i < 4 * W; i += TPB) s_in[i] = src[i];

    // Stage weights, duplicated into both f32x2 lanes.
    for (int i = tid; i < OC * 9; i += TPB) {
        int o = i / 9;
        int k = i - o * 9;
        float w = weight[i];
        s_w[o * 10 + k] = pack2(w, w);
    }
    __syncthreads();

    const int r = tid / 112;          // output row within block
    const int s = tid - r * 112;      // pair slot
    if (s >= 111) return;             // 111 pairs cover WO=222 exactly
    const int x = 2 * s;

    // 9 packed sliding-pair operands: rows r..r+2, cols x..x+3.
    const float* rowp = s_in + r * W + x;
    ull P[9];
#pragma unroll
    for (int rr = 0; rr < 3; ++rr) {
        float a0 = rowp[rr * W + 0];
        float a1 = rowp[rr * W + 1];
        float a2 = rowp[rr * W + 2];
        float a3 = rowp[rr * W + 3];
        P[rr * 3 + 0] = pack2(a0, a1);
        P[rr * 3 + 1] = pack2(a1, a2);
        P[rr * 3 + 2] = pack2(a2, a3);
    }

    const size_t plane = (size_t)HO * WO;
    float* op = out + (((size_t)b * OC) * HO + (y0 + r)) * WO + x;
    const ulonglong2* w2 = reinterpret_cast<const ulonglong2*>(s_w);

#pragma unroll 2
    for (int o = 0; o < OC; ++o) {
        const ulonglong2* wo = w2 + o * 5;
        ulonglong2 w01 = wo[0];
        ulonglong2 w23 = wo[1];
        ulonglong2 w45 = wo[2];
        ulonglong2 w67 = wo[3];
        ulonglong2 w8x = wo[4];   // .y is padding, never used

        ull acc = 0ull;           // packed (0.0f, 0.0f)
        FMA2(acc, P[0], w01.x, acc);
        FMA2(acc, P[1], w01.y, acc);
        FMA2(acc, P[2], w23.x, acc);
        FMA2(acc, P[3], w23.y, acc);
        FMA2(acc, P[4], w45.x, acc);
        FMA2(acc, P[5], w45.y, acc);
        FMA2(acc, P[6], w67.x, acc);
        FMA2(acc, P[7], w67.y, acc);
        FMA2(acc, P[8], w8x.x, acc);

        *reinterpret_cast<ull*>(op) = acc;  // STG.64, 8B-aligned, coalesced
        op += plane;
    }
}

extern "C" void kernel_launch(void* const* d_in, const int* in_sizes, int n_in,
                              void* d_out, int out_size) {
    const float* data   = (const float*)d_in[0];
    const float* weight = (const float*)d_in[1];
    float* out          = (float*)d_out;

    dim3 grid(HO / 2, 32);   // (111, 32)
    Conv2d_68298569941797_kernel<<<grid, TPB>>>(data, weight, out);
}